// round 12
// baseline (speedup 1.0000x reference)
#include <cuda_runtime.h>
#include <cstdint>
#include <cstddef>

// GRU decoder: B=256, T=1024, H=256, D=96 (obs32|y32|z32), O=32.
// 16 clusters x 8 CTAs x 128 threads. Each CTA owns 32 hidden units,
// weights resident in SMEM; cluster exchanges h/y via DSMEM each step.

#define CSIZE    8
#define NTHREADS 128
#define TSTEPS   1024
#define GB       16
#define TO32     32768   // T*O

// shared layout (float offsets)
#define OFF_W4   0          // float4[320][32]  -> 40960 floats
#define OFF_XH   40960      // float[2][320][16]-> 10240 floats
#define OFF_CST  51200      // float[4][512]
#define OFF_WOT  53248      // float[32][32]
#define OFF_STG  54272      // float[8][2][32]
#define OFF_BOUT 54784      // float[32]
#define SMEM_FLOATS 54816
#define SMEM_BYTES  (SMEM_FLOATS * 4)

__device__ __forceinline__ uint32_t smem_u32(const void* p) {
    return (uint32_t)__cvta_generic_to_shared(p);
}
__device__ __forceinline__ uint32_t mapa_rk(uint32_t a, uint32_t r) {
    uint32_t d;
    asm("mapa.shared::cluster.u32 %0, %1, %2;" : "=r"(d) : "r"(a), "r"(r));
    return d;
}
__device__ __forceinline__ void stc(uint32_t a, float v) {
    asm volatile("st.shared::cluster.f32 [%0], %1;" :: "r"(a), "f"(v) : "memory");
}
__device__ __forceinline__ void cluster_sync_() {
    asm volatile("barrier.cluster.arrive.aligned;" ::: "memory");
    asm volatile("barrier.cluster.wait.aligned;"   ::: "memory");
}
__device__ __forceinline__ uint32_t ctarank_() {
    uint32_t r; asm("mov.u32 %0, %%cluster_ctarank;" : "=r"(r)); return r;
}
__device__ __forceinline__ float sigf(float x) {
    return 1.0f / (1.0f + expf(-x));
}

extern "C" __global__ void __launch_bounds__(NTHREADS, 1)
__cluster_dims__(CSIZE, 1, 1)
gru_cluster_kernel(const float* __restrict__ init_y,
                   const float* __restrict__ obs,
                   const float* __restrict__ z_dyn,
                   const float* __restrict__ W_ih,   // (768,96)
                   const float* __restrict__ W_hh,   // (768,256)
                   const float* __restrict__ b_ih,
                   const float* __restrict__ b_hh,
                   const float* __restrict__ W_out,  // (32,256)
                   const float* __restrict__ b_out,
                   float* __restrict__ out)          // (256,1024,32)
{
    extern __shared__ float sm[];
    float4* W4 = (float4*)(sm + OFF_W4);

    const int tid = threadIdx.x;
    const int R   = (int)ctarank_();
    const int B0  = (blockIdx.x >> 3) * GB;

    // DSMEM base addresses for each rank
    uint32_t rb[CSIZE];
    const uint32_t my_base = smem_u32(sm);
    #pragma unroll
    for (int r = 0; r < CSIZE; r++) rb[r] = mapa_rk(my_base, r);

    // ---- one-time setup ----
    // packed weights: k<256 -> W_hh col k; k in [256,320) -> W_ih col (k-256)
    for (int e = tid; e < 32 * 320; e += NTHREADS) {
        int il = e / 320, k = e % 320;
        int gi = R * 32 + il;
        float wr, wz, wn;
        if (k < 256) {
            wr = W_hh[(size_t)gi * 256 + k];
            wz = W_hh[(size_t)(256 + gi) * 256 + k];
            wn = W_hh[(size_t)(512 + gi) * 256 + k];
        } else {
            int j = k - 256;
            wr = W_ih[(size_t)gi * 96 + j];
            wz = W_ih[(size_t)(256 + gi) * 96 + j];
            wn = W_ih[(size_t)(512 + gi) * 96 + j];
        }
        W4[k * 32 + il] = make_float4(wr, wz, wn, 0.0f);
    }
    // per-(il,b) constants: biases + z_dyn contribution
    for (int e = tid; e < 512; e += NTHREADS) {
        int il = e >> 4, b = e & 15;
        int gi = R * 32 + il, gb = B0 + b;
        float cr  = b_ih[gi]       + b_hh[gi];
        float cz  = b_ih[256 + gi] + b_hh[256 + gi];
        float cxn = b_ih[512 + gi];
        float chn = b_hh[512 + gi];
        for (int j = 0; j < 32; j++) {
            float zv = z_dyn[(size_t)gb * 32 + j];
            cr  = fmaf(W_ih[(size_t)gi * 96 + 64 + j],         zv, cr);
            cz  = fmaf(W_ih[(size_t)(256 + gi) * 96 + 64 + j], zv, cz);
            cxn = fmaf(W_ih[(size_t)(512 + gi) * 96 + 64 + j], zv, cxn);
        }
        sm[OFF_CST + e]        = cr;
        sm[OFF_CST + 512 + e]  = cz;
        sm[OFF_CST + 1024 + e] = cxn;
        sm[OFF_CST + 1536 + e] = chn;
    }
    // W_out slice: WOT[il][o] = W_out[o][R*32+il]
    for (int e = tid; e < 1024; e += NTHREADS) {
        int il = e >> 5, o = e & 31;
        sm[OFF_WOT + e] = W_out[(size_t)o * 256 + R * 32 + il];
    }
    if (tid < 32) sm[OFF_BOUT + tid] = b_out[tid];
    // XH buffer 0: h0=0, obs[t=0], y_prev=init_y
    for (int e = tid; e < 4096; e += NTHREADS) sm[OFF_XH + e] = 0.0f; // rows 0..255
    for (int e = tid; e < 512; e += NTHREADS) {
        int b = e >> 5, j = e & 31;
        sm[OFF_XH + (256 + j) * 16 + b] = obs[(size_t)(B0 + b) * TO32 + j];
        sm[OFF_XH + (288 + j) * 16 + b] = init_y[(size_t)(B0 + b) * 32 + j];
    }
    __syncthreads();
    cluster_sync_();

    const int c  = tid & 3;        // batch sub-group: b = 4c..4c+3
    const int il = tid >> 2;       // local hidden index 0..31
    const int hrow = R * 32 + il;
    const int pb = tid >> 3;       // y-partial batch 0..15
    const int po = (tid & 7) * 4;  // y-partial out col base

    for (int t = 0; t < TSTEPS; t++) {
        const int curb = OFF_XH + (t & 1) * 5120;
        const int nxtb = OFF_XH + ((t & 1) ^ 1) * 5120;

        // ---- phase 1: gate accumulation ----
        float aR[4] = {0, 0, 0, 0}, aZ[4] = {0, 0, 0, 0};
        float aH[4] = {0, 0, 0, 0}, aX[4] = {0, 0, 0, 0};
        const float4* Wp = W4 + il;
        const float*  Xp = sm + curb + 4 * c;
        #pragma unroll 8
        for (int k = 0; k < 256; k++) {
            float4 w  = Wp[k * 32];
            float4 xh = *(const float4*)(Xp + k * 16);
            aR[0] = fmaf(w.x, xh.x, aR[0]); aZ[0] = fmaf(w.y, xh.x, aZ[0]); aH[0] = fmaf(w.z, xh.x, aH[0]);
            aR[1] = fmaf(w.x, xh.y, aR[1]); aZ[1] = fmaf(w.y, xh.y, aZ[1]); aH[1] = fmaf(w.z, xh.y, aH[1]);
            aR[2] = fmaf(w.x, xh.z, aR[2]); aZ[2] = fmaf(w.y, xh.z, aZ[2]); aH[2] = fmaf(w.z, xh.z, aH[2]);
            aR[3] = fmaf(w.x, xh.w, aR[3]); aZ[3] = fmaf(w.y, xh.w, aZ[3]); aH[3] = fmaf(w.z, xh.w, aH[3]);
        }
        #pragma unroll 8
        for (int k = 256; k < 320; k++) {
            float4 w  = Wp[k * 32];
            float4 xh = *(const float4*)(Xp + k * 16);
            aR[0] = fmaf(w.x, xh.x, aR[0]); aZ[0] = fmaf(w.y, xh.x, aZ[0]); aX[0] = fmaf(w.z, xh.x, aX[0]);
            aR[1] = fmaf(w.x, xh.y, aR[1]); aZ[1] = fmaf(w.y, xh.y, aZ[1]); aX[1] = fmaf(w.z, xh.y, aX[1]);
            aR[2] = fmaf(w.x, xh.z, aR[2]); aZ[2] = fmaf(w.y, xh.z, aZ[2]); aX[2] = fmaf(w.z, xh.z, aX[2]);
            aR[3] = fmaf(w.x, xh.w, aR[3]); aZ[3] = fmaf(w.y, xh.w, aZ[3]); aX[3] = fmaf(w.z, xh.w, aX[3]);
        }

        // ---- phase 2: activations, h_new local + broadcast to 7 peers ----
        #pragma unroll
        for (int u = 0; u < 4; u++) {
            int b = 4 * c + u;
            int ci = il * 16 + b;
            float r  = sigf(aR[u] + sm[OFF_CST + ci]);
            float zg = sigf(aZ[u] + sm[OFF_CST + 512 + ci]);
            float n  = tanhf(aX[u] + sm[OFF_CST + 1024 + ci] + r * (aH[u] + sm[OFF_CST + 1536 + ci]));
            float hp = sm[curb + hrow * 16 + b];
            float h  = n + zg * (hp - n);
            int off  = nxtb + hrow * 16 + b;
            sm[off]  = h;
            uint32_t boff = (uint32_t)off * 4u;
            #pragma unroll
            for (int rr = 0; rr < CSIZE; rr++)
                if (rr != R) stc(rb[rr] + boff, h);
        }
        // obs for step t+1 (local)
        if (t + 1 < TSTEPS) {
            #pragma unroll
            for (int i = 0; i < 4; i++) {
                int e = tid + 128 * i;
                int b = e >> 5, j = e & 31;
                sm[nxtb + (256 + j) * 16 + b] =
                    obs[(size_t)(B0 + b) * TO32 + (size_t)(t + 1) * 32 + j];
            }
        }
        __syncthreads();

        // ---- y partials: this CTA's 32-unit contribution for all 16 b ----
        {
            float p0 = 0, p1 = 0, p2 = 0, p3 = 0;
            const float* hb = sm + nxtb + (R * 32) * 16 + pb;
            const float* wo = sm + OFF_WOT + po;
            #pragma unroll 8
            for (int i2 = 0; i2 < 32; i2++) {
                float hv = hb[i2 * 16];
                float4 w = *(const float4*)(wo + i2 * 32);
                p0 = fmaf(hv, w.x, p0); p1 = fmaf(hv, w.y, p1);
                p2 = fmaf(hv, w.z, p2); p3 = fmaf(hv, w.w, p3);
            }
            int owner = pb >> 1;
            int soff  = OFF_STG + (R * 2 + (pb & 1)) * 32 + po;
            if (owner == R) {
                sm[soff] = p0; sm[soff + 1] = p1; sm[soff + 2] = p2; sm[soff + 3] = p3;
            } else {
                uint32_t a = rb[owner] + (uint32_t)soff * 4u;
                stc(a, p0); stc(a + 4, p1); stc(a + 8, p2); stc(a + 12, p3);
            }
        }
        cluster_sync_();

        // ---- y finalize for owned batches (2R, 2R+1), write out + broadcast ----
        if (tid < 64) {
            int bb = tid >> 5, o = tid & 31;
            float y = sm[OFF_BOUT + o];
            #pragma unroll
            for (int src = 0; src < CSIZE; src++)
                y += sm[OFF_STG + (src * 2 + bb) * 32 + o];
            int gb = B0 + 2 * R + bb;
            out[(size_t)gb * TO32 + (size_t)t * 32 + o] = y;
            int off = nxtb + (288 + o) * 16 + 2 * R + bb;
            sm[off] = y;
            uint32_t boff = (uint32_t)off * 4u;
            #pragma unroll
            for (int rr = 0; rr < CSIZE; rr++)
                if (rr != R) stc(rb[rr] + boff, y);
        }
        cluster_sync_();
    }
}

extern "C" void kernel_launch(void* const* d_in, const int* in_sizes, int n_in,
                              void* d_out, int out_size) {
    (void)in_sizes; (void)n_in; (void)out_size;
    static bool attr_set = false;
    if (!attr_set) {
        cudaFuncSetAttribute(gru_cluster_kernel,
                             cudaFuncAttributeMaxDynamicSharedMemorySize, SMEM_BYTES);
        attr_set = true;
    }
    gru_cluster_kernel<<<128, NTHREADS, SMEM_BYTES>>>(
        (const float*)d_in[0], (const float*)d_in[1], (const float*)d_in[2],
        (const float*)d_in[3], (const float*)d_in[4], (const float*)d_in[5],
        (const float*)d_in[6], (const float*)d_in[7], (const float*)d_in[8],
        (float*)d_out);
}

// round 13
// speedup vs baseline: 1.4736x; 1.4736x over previous
#include <cuda_runtime.h>
#include <cstdint>
#include <cstddef>

// GRU decoder: B=256, T=1024, H=256, D=96 (obs32|y32|z32), O=32.
// 16 clusters x 8 CTAs x 256 threads. Each CTA owns 32 hidden units with
// weights resident in SMEM. Threads split the k-reduction in half
// (2 warps/SMSP for latency hiding), gate math uses packed fma.rn.f32x2.
// h/y exchanged across the cluster via st.shared::cluster each step.

#define CSIZE    8
#define NTHREADS 256
#define TSTEPS   1024
#define GB       16
#define TO32     32768   // T*O

typedef unsigned long long ull;

// shared layout (float offsets)
#define OFF_W4   0          // float4[320][32]   -> 40960 floats
#define OFF_XH   40960      // float[2][320][16] -> 10240
#define OFF_CST  51200      // float[4][512]     -> 2048
#define OFF_WOT  53248      // float[32][32]     -> 1024
#define OFF_STG  54272      // float[8][2][32]   -> 512
#define OFF_BOUT 54784      // float[32]
#define OFF_RED  54816      // ull[8][128]       -> 2048 floats
#define SMEM_FLOATS 56864
#define SMEM_BYTES  (SMEM_FLOATS * 4)   // 227456

__device__ __forceinline__ uint32_t smem_u32(const void* p) {
    return (uint32_t)__cvta_generic_to_shared(p);
}
__device__ __forceinline__ uint32_t mapa_rk(uint32_t a, uint32_t r) {
    uint32_t d;
    asm("mapa.shared::cluster.u32 %0, %1, %2;" : "=r"(d) : "r"(a), "r"(r));
    return d;
}
__device__ __forceinline__ void stc(uint32_t a, float v) {
    asm volatile("st.shared::cluster.f32 [%0], %1;" :: "r"(a), "f"(v) : "memory");
}
__device__ __forceinline__ void stc4(uint32_t a, float4 q) {
    asm volatile("st.shared::cluster.v4.f32 [%0], {%1,%2,%3,%4};"
                 :: "r"(a), "f"(q.x), "f"(q.y), "f"(q.z), "f"(q.w) : "memory");
}
__device__ __forceinline__ void cluster_sync_() {
    asm volatile("barrier.cluster.arrive.aligned;" ::: "memory");
    asm volatile("barrier.cluster.wait.aligned;"   ::: "memory");
}
__device__ __forceinline__ uint32_t ctarank_() {
    uint32_t r; asm("mov.u32 %0, %%cluster_ctarank;" : "=r"(r)); return r;
}
__device__ __forceinline__ ull dup2(float v) {
    ull d; uint32_t u = __float_as_uint(v);
    asm("mov.b64 %0, {%1, %1};" : "=l"(d) : "r"(u));
    return d;
}
__device__ __forceinline__ void fma2(ull& acc, ull a, ull b) {
    asm("fma.rn.f32x2 %0, %1, %2, %0;" : "+l"(acc) : "l"(a), "l"(b));
}
__device__ __forceinline__ void add2(ull& a, ull b) {
    asm("add.rn.f32x2 %0, %0, %1;" : "+l"(a) : "l"(b));
}
__device__ __forceinline__ float2 unpk(ull p) {
    float2 r;
    asm("mov.b64 {%0, %1}, %2;" : "=f"(r.x), "=f"(r.y) : "l"(p));
    return r;
}
__device__ __forceinline__ float sigf(float x) {
    return __fdividef(1.0f, 1.0f + __expf(-x));
}
__device__ __forceinline__ float tanhf_(float x) {
    float e = __expf(-2.0f * x);
    return __fdividef(1.0f - e, 1.0f + e);
}

extern "C" __global__ void __launch_bounds__(NTHREADS, 1)
__cluster_dims__(CSIZE, 1, 1)
gru_cluster_kernel(const float* __restrict__ init_y,
                   const float* __restrict__ obs,
                   const float* __restrict__ z_dyn,
                   const float* __restrict__ W_ih,   // (768,96)
                   const float* __restrict__ W_hh,   // (768,256)
                   const float* __restrict__ b_ih,
                   const float* __restrict__ b_hh,
                   const float* __restrict__ W_out,  // (32,256)
                   const float* __restrict__ b_out,
                   float* __restrict__ out)          // (256,1024,32)
{
    extern __shared__ float sm[];
    float4* W4  = (float4*)(sm + OFF_W4);
    ull*    RED = (ull*)(sm + OFF_RED);

    const int tid = threadIdx.x;
    const int R   = (int)ctarank_();
    const int B0  = (blockIdx.x >> 3) * GB;

    uint32_t rb[CSIZE];
    const uint32_t my_base = smem_u32(sm);
    #pragma unroll
    for (int r = 0; r < CSIZE; r++) rb[r] = mapa_rk(my_base, r);

    // ---- one-time setup ----
    for (int e = tid; e < 32 * 320; e += NTHREADS) {
        int il = e / 320, k = e % 320;
        int gi = R * 32 + il;
        float wr, wz, wn;
        if (k < 256) {
            wr = W_hh[(size_t)gi * 256 + k];
            wz = W_hh[(size_t)(256 + gi) * 256 + k];
            wn = W_hh[(size_t)(512 + gi) * 256 + k];
        } else {
            int j = k - 256;
            wr = W_ih[(size_t)gi * 96 + j];
            wz = W_ih[(size_t)(256 + gi) * 96 + j];
            wn = W_ih[(size_t)(512 + gi) * 96 + j];
        }
        W4[k * 32 + il] = make_float4(wr, wz, wn, 0.0f);
    }
    for (int e = tid; e < 512; e += NTHREADS) {
        int il = e >> 4, b = e & 15;
        int gi = R * 32 + il, gb = B0 + b;
        float cr  = b_ih[gi]       + b_hh[gi];
        float cz  = b_ih[256 + gi] + b_hh[256 + gi];
        float cxn = b_ih[512 + gi];
        float chn = b_hh[512 + gi];
        for (int j = 0; j < 32; j++) {
            float zv = z_dyn[(size_t)gb * 32 + j];
            cr  = fmaf(W_ih[(size_t)gi * 96 + 64 + j],         zv, cr);
            cz  = fmaf(W_ih[(size_t)(256 + gi) * 96 + 64 + j], zv, cz);
            cxn = fmaf(W_ih[(size_t)(512 + gi) * 96 + 64 + j], zv, cxn);
        }
        sm[OFF_CST + e]        = cr;
        sm[OFF_CST + 512 + e]  = cz;
        sm[OFF_CST + 1024 + e] = cxn;
        sm[OFF_CST + 1536 + e] = chn;
    }
    for (int e = tid; e < 1024; e += NTHREADS) {
        int il = e >> 5, o = e & 31;
        sm[OFF_WOT + e] = W_out[(size_t)o * 256 + R * 32 + il];
    }
    if (tid < 32) sm[OFF_BOUT + tid] = b_out[tid];
    for (int e = tid; e < 4096; e += NTHREADS) sm[OFF_XH + e] = 0.0f;
    for (int e = tid; e < 512; e += NTHREADS) {
        int b = e >> 5, j = e & 31;
        sm[OFF_XH + (256 + j) * 16 + b] = obs[(size_t)(B0 + b) * TO32 + j];
        sm[OFF_XH + (288 + j) * 16 + b] = init_y[(size_t)(B0 + b) * 32 + j];
    }
    __syncthreads();
    cluster_sync_();

    const int th   = tid & 127;
    const int c    = th & 3;        // batch group (4 batches)
    const int il   = th >> 2;       // local hidden index
    const int half = tid >> 7;      // k-split half
    const int hrow = R * 32 + il;
    const int k0   = half * 160;
    const int kmid = 160 + 96 * half;
    const int kend = 160 + 160 * half;
    const int pb   = tid >> 3;      // y-partial batch (tid<128)
    const int po   = (tid & 7) * 4; // y-partial out col base

    for (int t = 0; t < TSTEPS; t++) {
        const int curb = OFF_XH + (t & 1) * 5120;
        const int nxtb = OFF_XH + ((t & 1) ^ 1) * 5120;

        // obs(t+1) prefetch into registers (upper half threads)
        float4 ov = make_float4(0.f, 0.f, 0.f, 0.f);
        int ob = th >> 3, oj = (th & 7) * 4;
        if (half && (t + 1 < TSTEPS))
            ov = *(const float4*)(obs + (size_t)(B0 + ob) * TO32
                                      + (size_t)(t + 1) * 32 + oj);

        // ---- phase 1: gate accumulation (packed f32x2) ----
        ull aR01 = 0, aR23 = 0, aZ01 = 0, aZ23 = 0;
        ull aH01 = 0, aH23 = 0, aX01 = 0, aX23 = 0;
        const float4* Wp = W4 + il;
        const char*   Xb = (const char*)(sm + curb + 4 * c);
        #pragma unroll 8
        for (int k = k0; k < kmid; k++) {
            float4 w = Wp[k * 32];
            ulonglong2 x = *(const ulonglong2*)(Xb + (size_t)k * 64);
            ull wr2 = dup2(w.x), wz2 = dup2(w.y), wn2 = dup2(w.z);
            fma2(aR01, wr2, x.x); fma2(aR23, wr2, x.y);
            fma2(aZ01, wz2, x.x); fma2(aZ23, wz2, x.y);
            fma2(aH01, wn2, x.x); fma2(aH23, wn2, x.y);
        }
        #pragma unroll 8
        for (int k = kmid; k < kend; k++) {
            float4 w = Wp[k * 32];
            ulonglong2 x = *(const ulonglong2*)(Xb + (size_t)k * 64);
            ull wr2 = dup2(w.x), wz2 = dup2(w.y), wn2 = dup2(w.z);
            fma2(aR01, wr2, x.x); fma2(aR23, wr2, x.y);
            fma2(aZ01, wz2, x.x); fma2(aZ23, wz2, x.y);
            fma2(aX01, wn2, x.x); fma2(aX23, wn2, x.y);
        }

        if (half) {
            RED[0 * 128 + th] = aR01; RED[1 * 128 + th] = aR23;
            RED[2 * 128 + th] = aZ01; RED[3 * 128 + th] = aZ23;
            RED[4 * 128 + th] = aH01; RED[5 * 128 + th] = aH23;
            RED[6 * 128 + th] = aX01; RED[7 * 128 + th] = aX23;
            if (t + 1 < TSTEPS) {
                int base = nxtb + (256 + oj) * 16 + ob;
                sm[base]      = ov.x; sm[base + 16] = ov.y;
                sm[base + 32] = ov.z; sm[base + 48] = ov.w;
            }
        }
        __syncthreads();

        // ---- phase 2: combine halves, activations, h broadcast (half 0) ----
        if (!half) {
            add2(aR01, RED[0 * 128 + th]); add2(aR23, RED[1 * 128 + th]);
            add2(aZ01, RED[2 * 128 + th]); add2(aZ23, RED[3 * 128 + th]);
            add2(aH01, RED[4 * 128 + th]); add2(aH23, RED[5 * 128 + th]);
            add2(aX01, RED[6 * 128 + th]); add2(aX23, RED[7 * 128 + th]);
            float2 r01 = unpk(aR01), r23 = unpk(aR23);
            float2 z01 = unpk(aZ01), z23 = unpk(aZ23);
            float2 g01 = unpk(aH01), g23 = unpk(aH23);
            float2 x01 = unpk(aX01), x23 = unpk(aX23);
            float aRv[4] = {r01.x, r01.y, r23.x, r23.y};
            float aZv[4] = {z01.x, z01.y, z23.x, z23.y};
            float aHv[4] = {g01.x, g01.y, g23.x, g23.y};
            float aXv[4] = {x01.x, x01.y, x23.x, x23.y};
            float4 hq;
            float* hqp = &hq.x;
            #pragma unroll
            for (int u = 0; u < 4; u++) {
                int b  = 4 * c + u;
                int ci = il * 16 + b;
                float r  = sigf(aRv[u] + sm[OFF_CST + ci]);
                float zg = sigf(aZv[u] + sm[OFF_CST + 512 + ci]);
                float n  = tanhf_(aXv[u] + sm[OFF_CST + 1024 + ci]
                                 + r * (aHv[u] + sm[OFF_CST + 1536 + ci]));
                float hp = sm[curb + hrow * 16 + b];
                hqp[u]   = n + zg * (hp - n);
            }
            int off = nxtb + hrow * 16 + 4 * c;
            *(float4*)(sm + off) = hq;
            uint32_t boff = (uint32_t)off * 4u;
            #pragma unroll
            for (int rr = 0; rr < CSIZE; rr++)
                if (rr != R) stc4(rb[rr] + boff, hq);
        }
        __syncthreads();

        // ---- y partials: own 32-unit slice, all 16 batches (tid<128) ----
        if (tid < 128) {
            float p0 = 0, p1 = 0, p2 = 0, p3 = 0;
            const float* hb = sm + nxtb + (R * 32) * 16 + pb;
            const float* wo = sm + OFF_WOT + po;
            #pragma unroll 8
            for (int i2 = 0; i2 < 32; i2++) {
                float hv = hb[i2 * 16];
                float4 w = *(const float4*)(wo + i2 * 32);
                p0 = fmaf(hv, w.x, p0); p1 = fmaf(hv, w.y, p1);
                p2 = fmaf(hv, w.z, p2); p3 = fmaf(hv, w.w, p3);
            }
            int owner = pb >> 1;
            int soff  = OFF_STG + (R * 2 + (pb & 1)) * 32 + po;
            if (owner == R) {
                sm[soff] = p0; sm[soff + 1] = p1;
                sm[soff + 2] = p2; sm[soff + 3] = p3;
            } else {
                stc4(rb[owner] + (uint32_t)soff * 4u, make_float4(p0, p1, p2, p3));
            }
        }
        cluster_sync_();

        // ---- y finalize for owned batches (2R, 2R+1) ----
        if (tid < 64) {
            int bb = tid >> 5, o = tid & 31;
            float y = sm[OFF_BOUT + o];
            #pragma unroll
            for (int src = 0; src < CSIZE; src++)
                y += sm[OFF_STG + (src * 2 + bb) * 32 + o];
            int gb = B0 + 2 * R + bb;
            out[(size_t)gb * TO32 + (size_t)t * 32 + o] = y;
            int off = nxtb + (288 + o) * 16 + 2 * R + bb;
            sm[off] = y;
            uint32_t boff = (uint32_t)off * 4u;
            #pragma unroll
            for (int rr = 0; rr < CSIZE; rr++)
                if (rr != R) stc(rb[rr] + boff, y);
        }
        cluster_sync_();
    }
}

extern "C" void kernel_launch(void* const* d_in, const int* in_sizes, int n_in,
                              void* d_out, int out_size) {
    (void)in_sizes; (void)n_in; (void)out_size;
    static bool attr_set = false;
    if (!attr_set) {
        cudaFuncSetAttribute(gru_cluster_kernel,
                             cudaFuncAttributeMaxDynamicSharedMemorySize, SMEM_BYTES);
        attr_set = true;
    }
    gru_cluster_kernel<<<128, NTHREADS, SMEM_BYTES>>>(
        (const float*)d_in[0], (const float*)d_in[1], (const float*)d_in[2],
        (const float*)d_in[3], (const float*)d_in[4], (const float*)d_in[5],
        (const float*)d_in[6], (const float*)d_in[7], (const float*)d_in[8],
        (float*)d_out);
}